// round 6
// baseline (speedup 1.0000x reference)
#include <cuda_runtime.h>

// Quanvolution (2x2, 4 qubits, RY encode + RY params + CNOT ring, <Z_q>).
//
// Closed form per output pixel (x,y):
//   Zq = cos(pi*a_q + w_q)   computed DIRECTLY via one MUFU.COS per (elem,q)
//   ch0 = Z1*Z2*Z3, ch1 = Z0*Z1, ch2 = Z0*Z1*Z2, ch3 = Z0*Z1*Z2*Z3
//
// R6: direct-cos loader (no weight trig, no sincos+fold), weights via one
// float4 LDG; consumer products in packed f32x2; transposed tables + aligned
// LDS.128 + coalesced STG retained from R5.

#define H_IN 224
#define W_IN 224
#define L_OUT 223
#define TILE 32
#define RPAD 36            // row-dim stride (floats): 4c-mod-32 bank pattern, conflict-free
#define PI_F 3.14159265358979323846f

union F4U {
    float4 f;
    float a[4];
    unsigned long long u[2];
};

__device__ __forceinline__ unsigned long long mul2(unsigned long long a,
                                                   unsigned long long b) {
    unsigned long long r;
    asm("mul.rn.f32x2 %0, %1, %2;" : "=l"(r) : "l"(a), "l"(b));
    return r;
}

__global__ __launch_bounds__(256) void quanv_main_kernel(
    const float* __restrict__ in,   // (64,1,224,224)
    const float* __restrict__ w,    // (1,4)
    float* __restrict__ out)        // (64,4,223,223)
{
    // Tq[c][r] (transposed: rows contiguous):
    //   T0[c][r] = Z_w0(row r,   col c)
    //   T1[c][r] = Z_w1(row r,   col c+1)
    //   T2[c][r] = Z_w2(row r+1, col c)
    //   T3[c][r] = Z_w3(row r+1, col c+1)
    __shared__ float T0[TILE][RPAD];
    __shared__ float T1[TILE][RPAD];
    __shared__ float T2[TILE][RPAD];
    __shared__ float T3[TILE][RPAD];

    const int tid = threadIdx.x;
    const int b  = blockIdx.z;
    const int x0 = blockIdx.y * TILE;
    const int y0 = blockIdx.x * TILE;

    const float4 wv = __ldg(reinterpret_cast<const float4*>(w));  // w0..w3

    const float* inb = in + (size_t)b * (H_IN * W_IN);

    const int c  = tid & 31;   // column within tile (lane -> consecutive y)
    const int g  = tid >> 5;   // 0..7
    const int rb = g << 2;     // row-strip base

    // ---- Loader: source column c, rows rb..rb+4 ----
    {
        float v[5];
        #pragma unroll
        for (int j = 0; j < 5; j++) {
            const int gx = x0 + rb + j, gy = y0 + c;
            v[j] = (gx < H_IN && gy < W_IN) ? __ldg(&inb[gx * W_IN + gy]) : 0.0f;
        }
        float4 t;
        t.x = __cosf(fmaf(v[0], PI_F, wv.x));
        t.y = __cosf(fmaf(v[1], PI_F, wv.x));
        t.z = __cosf(fmaf(v[2], PI_F, wv.x));
        t.w = __cosf(fmaf(v[3], PI_F, wv.x));
        *reinterpret_cast<float4*>(&T0[c][rb]) = t;
        t.x = __cosf(fmaf(v[1], PI_F, wv.z));
        t.y = __cosf(fmaf(v[2], PI_F, wv.z));
        t.z = __cosf(fmaf(v[3], PI_F, wv.z));
        t.w = __cosf(fmaf(v[4], PI_F, wv.z));
        *reinterpret_cast<float4*>(&T2[c][rb]) = t;
        if (c > 0) {
            t.x = __cosf(fmaf(v[0], PI_F, wv.y));
            t.y = __cosf(fmaf(v[1], PI_F, wv.y));
            t.z = __cosf(fmaf(v[2], PI_F, wv.y));
            t.w = __cosf(fmaf(v[3], PI_F, wv.y));
            *reinterpret_cast<float4*>(&T1[c - 1][rb]) = t;
            t.x = __cosf(fmaf(v[1], PI_F, wv.w));
            t.y = __cosf(fmaf(v[2], PI_F, wv.w));
            t.z = __cosf(fmaf(v[3], PI_F, wv.w));
            t.w = __cosf(fmaf(v[4], PI_F, wv.w));
            *reinterpret_cast<float4*>(&T3[c - 1][rb]) = t;
        }
    }
    // ---- Extra pass: source column 32 feeds T1[31], T3[31] ----
    if (tid < 8) {
        const int rb2 = tid << 2;
        float v[5];
        #pragma unroll
        for (int j = 0; j < 5; j++) {
            const int gx = x0 + rb2 + j, gy = y0 + 32;
            v[j] = (gx < H_IN && gy < W_IN) ? __ldg(&inb[gx * W_IN + gy]) : 0.0f;
        }
        float4 t;
        t.x = __cosf(fmaf(v[0], PI_F, wv.y));
        t.y = __cosf(fmaf(v[1], PI_F, wv.y));
        t.z = __cosf(fmaf(v[2], PI_F, wv.y));
        t.w = __cosf(fmaf(v[3], PI_F, wv.y));
        *reinterpret_cast<float4*>(&T1[31][rb2]) = t;
        t.x = __cosf(fmaf(v[1], PI_F, wv.w));
        t.y = __cosf(fmaf(v[2], PI_F, wv.w));
        t.z = __cosf(fmaf(v[3], PI_F, wv.w));
        t.w = __cosf(fmaf(v[4], PI_F, wv.w));
        *reinterpret_cast<float4*>(&T3[31][rb2]) = t;
    }
    __syncthreads();

    // ---- Consumer: 4-row strip (rows rb..rb+3) at column c ----
    const int y = y0 + c;
    if (y >= L_OUT) return;

    F4U Z0, Z1, Z2, Z3;
    Z0.f = *reinterpret_cast<const float4*>(&T0[c][rb]);
    Z1.f = *reinterpret_cast<const float4*>(&T1[c][rb]);
    Z2.f = *reinterpret_cast<const float4*>(&T2[c][rb]);
    Z3.f = *reinterpret_cast<const float4*>(&T3[c][rb]);

    const size_t plane = (size_t)L_OUT * L_OUT;
    float* o = out + (size_t)b * 4 * plane + (size_t)(x0 + rb) * L_OUT + y;
    const bool full = (x0 + rb + 3) < L_OUT;   // whole quad in-range?

    #pragma unroll
    for (int h = 0; h < 2; h++) {              // half = pixel pair (j=2h, 2h+1)
        const unsigned long long p01 = mul2(Z0.u[h], Z1.u[h]);
        const unsigned long long p23 = mul2(Z2.u[h], Z3.u[h]);
        F4U C;                                  // C.u[0]=ch0 pair, C.u[1]=ch3 pair
        C.u[0] = mul2(Z1.u[h], p23);            // ch0 = Z1*Z2*Z3
        C.u[1] = mul2(p01, p23);                // ch3 = Z0*Z1*Z2*Z3
        F4U D;                                  // D.u[0]=ch1 pair, D.u[1]=ch2 pair
        D.u[0] = p01;                           // ch1 = Z0*Z1
        D.u[1] = mul2(p01, Z2.u[h]);            // ch2 = Z0*Z1*Z2

        #pragma unroll
        for (int k = 0; k < 2; k++) {
            const int j = 2 * h + k;
            if (full || (x0 + rb + j) < L_OUT) {
                float* oj = o + (size_t)j * L_OUT;
                oj[0]         = C.a[k];         // ch0
                oj[plane]     = D.a[k];         // ch1
                oj[2 * plane] = D.a[2 + k];     // ch2
                oj[3 * plane] = C.a[2 + k];     // ch3
            }
        }
    }
}

extern "C" void kernel_launch(void* const* d_in, const int* in_sizes, int n_in,
                              void* d_out, int out_size) {
    const float* inputs = (const float*)d_in[0];   // (64,1,224,224) float32
    const float* weight = (const float*)d_in[1];   // (1,4) float32
    float* out = (float*)d_out;                    // (64,4,223,223) float32

    dim3 grid((L_OUT + TILE - 1) / TILE,   // 7 (y tiles)
              (L_OUT + TILE - 1) / TILE,   // 7 (x tiles)
              64);                          // batch
    quanv_main_kernel<<<grid, 256>>>(inputs, weight, out);
}